// round 1
// baseline (speedup 1.0000x reference)
#include <cuda_runtime.h>

// ---------------- problem constants ----------------
#define BATCH   128
#define LTOT    720
#define FEAT    128
#define SEGL    24
#define WINN    15
#define NPREDK  4
#define DDIM    128
#define HDIM    512
#define NROWS   (BATCH*FEAT)          // 16384
#define EPSC    1e-6f
#define EPS2    1e-12f
#define MAXNC   0.99999f              // 1 - 1e-5
#define CLIPC   0.99999988f           // float32(1 - 1e-7)
#define DECAYF  0.9f

// t0 latents buffer: [k][bf][d]  (33.5 MB, device global scratch -- no allocs)
__device__ float g_t0[(size_t)NPREDK * NROWS * DDIM];

// ---------------- f32x2 packed-FMA helpers ----------------
static __device__ __forceinline__ unsigned long long pack2(float x, float y) {
    unsigned long long r;
    asm("mov.b64 %0, {%1,%2};" : "=l"(r) : "f"(x), "f"(y));
    return r;
}
static __device__ __forceinline__ void unpack2(unsigned long long a, float &x, float &y) {
    asm("mov.b64 {%0,%1}, %2;" : "=f"(x), "=f"(y) : "l"(a));
}
static __device__ __forceinline__ void fma2(unsigned long long &a,
                                            unsigned long long b,
                                            unsigned long long c) {
    asm("fma.rn.f32x2 %0, %1, %2, %0;" : "+l"(a) : "l"(b), "l"(c));
}

// ---------------- warp math helpers ----------------
static __device__ __forceinline__ float wred(float v) {
#pragma unroll
    for (int o = 16; o > 0; o >>= 1) v += __shfl_xor_sync(0xffffffffu, v, o);
    return v;
}

struct F4 { float x, y, z, w; };

static __device__ __forceinline__ float dotred(const F4 &a, const F4 &b) {
    return wred(a.x*b.x + a.y*b.y + a.z*b.z + a.w*b.w);
}

// logmap(x, y) on the Poincare ball (C=1):
//   d = mobius_add(-x, y);  n = ||d||;  lam = 2/max(1-|x|^2, eps)
//   return (2/lam) * artanh(n) * d / n
static __device__ __forceinline__ F4 logmap_f(const F4 &x, float sqx,
                                              const F4 &y, float sqy) {
    float xy  = dotred(x, y);
    float txy = -2.0f * xy;                 // 2 * dot(-x, y)
    float cx  = 1.0f + txy + sqy;           // coefficient on (-x)
    float cy  = 1.0f - sqx;                 // coefficient on y
    float den = fmaxf(1.0f + txy + sqx*sqy, EPSC);
    float inv = 1.0f / den;
    F4 d;
    d.x = (cy*y.x - cx*x.x) * inv;
    d.y = (cy*y.y - cx*x.y) * inv;
    d.z = (cy*y.z - cx*x.z) * inv;
    d.w = (cy*y.w - cx*x.w) * inv;
    float sqd = dotred(d, d);
    float nd  = sqrtf(fmaxf(sqd, EPS2));
    float s   = fmaxf(cy, EPSC) * atanhf(fminf(nd, CLIPC)) / nd;
    F4 r = { d.x*s, d.y*s, d.z*s, d.w*s };
    return r;
}

// expmap0(v) followed by _project; returns z and ||z||^2
static __device__ __forceinline__ void expmap0_f(const F4 &t, F4 &z, float &sqz) {
    float sq = dotred(t, t);
    float n  = sqrtf(fmaxf(sq, EPS2));
    float sc = tanhf(n) / n;
    F4 r = { t.x*sc, t.y*sc, t.z*sc, t.w*sc };
    float sqr = dotred(r, r);
    float nr  = sqrtf(fmaxf(sqr, EPS2));
    if (nr > MAXNC) {
        float s = MAXNC / nr;
        r.x *= s; r.y *= s; r.z *= s; r.w *= s;
        sqr *= s * s;
    }
    z = r; sqz = sqr;
}

// expmap(x, v) followed by _project; returns z and ||z||^2
static __device__ __forceinline__ void expmap_f(const F4 &x, float sqx, const F4 &v,
                                                F4 &zout, float &sqout) {
    float m   = fmaxf(1.0f - sqx, EPSC);    // 2/lam
    float sqv = dotred(v, v);
    float nv  = sqrtf(fmaxf(sqv, EPS2));
    float th  = tanhf(nv / m);              // tanh(lam*n/2)
    float sc  = th / nv;
    F4 sec = { v.x*sc, v.y*sc, v.z*sc, v.w*sc };
    float xy = dotred(x, sec);
    float y2 = dotred(sec, sec);
    float ca  = 1.0f + 2.0f*xy + y2;
    float cb  = 1.0f - sqx;
    float den = fmaxf(1.0f + 2.0f*xy + sqx*y2, EPSC);
    float inv = 1.0f / den;
    F4 r = { (ca*x.x + cb*sec.x)*inv, (ca*x.y + cb*sec.y)*inv,
             (ca*x.z + cb*sec.z)*inv, (ca*x.w + cb*sec.w)*inv };
    float sqr = dotred(r, r);
    float nr  = sqrtf(fmaxf(sqr, EPS2));
    if (nr > MAXNC) {
        float s = MAXNC / nr;
        r.x *= s; r.y *= s; r.z *= s; r.w *= s;
        sqr *= s * s;
    }
    zout = r; sqout = sqr;
}

// ============================================================================
// Kernel 1: fused tan-GEMV + expmap0 + hyperbolic velocity recurrence
// One warp per row (bf); each thread owns 4 of the 128 latent dims.
// ============================================================================
__global__ void __launch_bounds__(256)
latent_kernel(const float* __restrict__ trend,  const float* __restrict__ scoarse,
              const float* __restrict__ sfine,  const float* __restrict__ resid,
              const float* __restrict__ W_t, const float* __restrict__ b_t,
              const float* __restrict__ W_c, const float* __restrict__ b_c,
              const float* __restrict__ W_f, const float* __restrict__ b_f,
              const float* __restrict__ W_r, const float* __restrict__ b_r,
              const float* __restrict__ alpha_p)
{
    __shared__ float sX[8][480];   // per-warp: 4 streams x 120 timesteps
    __shared__ float s_w[16];

    const int tid  = threadIdx.x;
    const int wid  = tid >> 5;
    const int lane = tid & 31;

    if (tid == 0) {
        float ws[14]; float wv = 1.0f;
        for (int j = 13; j >= 0; --j) { ws[j] = wv; wv *= DECAYF; }
        float s = 0.0f;
        for (int j = 0; j < 14; ++j) s += ws[j];
        for (int j = 0; j < 14; ++j) s_w[j] = ws[j] / s;
    }
    __syncthreads();

    const int row = blockIdx.x * 8 + wid;
    const int b = row >> 7;
    const int f = row & 127;
    const size_t base = (size_t)b * LTOT * FEAT + f;
    const float* pt = trend   + base;
    const float* pc = scoarse + base;
    const float* pf = sfine   + base;
    const float* pr = resid   + base;

    // combined bias (b_t + b_c + b_f + b_r), 4 comps per thread
    F4 bias;
    {
        float4 t1 = __ldg(reinterpret_cast<const float4*>(b_t) + lane);
        float4 t2 = __ldg(reinterpret_cast<const float4*>(b_c) + lane);
        float4 t3 = __ldg(reinterpret_cast<const float4*>(b_f) + lane);
        float4 t4 = __ldg(reinterpret_cast<const float4*>(b_r) + lane);
        bias.x = t1.x + t2.x + t3.x + t4.x;
        bias.y = t1.y + t2.y + t3.y + t4.y;
        bias.z = t1.z + t2.z + t3.z + t4.z;
        bias.w = t1.w + t2.w + t3.w + t4.w;
    }
    const unsigned long long bias01 = pack2(bias.x, bias.y);
    const unsigned long long bias23 = pack2(bias.z, bias.w);

    F4 z_prev = {0,0,0,0}; float sq_prev = 0.0f;
    F4 avg = {0,0,0,0};
    F4 vel0 = {0,0,0,0}, vel1 = {0,0,0,0}, vel2 = {0,0,0,0};
    int slot = 0;

    for (int p = 0; p < 3; ++p) {
        __syncwarp();
        const int l0 = 360 + p * 120;   // 5 contiguous segments per pass
#pragma unroll
        for (int st = 0; st < 4; ++st) {
            const float* src = (st == 0 ? pt : st == 1 ? pc : st == 2 ? pf : pr);
            for (int i = lane; i < 120; i += 32)
                sX[wid][st * 120 + i] = __ldg(&src[(size_t)(l0 + i) * FEAT]);
        }
        __syncwarp();

        unsigned long long acc[5][2];
#pragma unroll
        for (int q = 0; q < 5; ++q) { acc[q][0] = bias01; acc[q][1] = bias23; }

#pragma unroll
        for (int st = 0; st < 4; ++st) {
            const float* W = (st == 0 ? W_t : st == 1 ? W_c : st == 2 ? W_f : W_r);
#pragma unroll 4
            for (int s = 0; s < SEGL; ++s) {
                ulonglong2 wv = __ldg(reinterpret_cast<const ulonglong2*>(W + s * DDIM) + lane);
#pragma unroll
                for (int q = 0; q < 5; ++q) {
                    float xv = sX[wid][st * 120 + q * SEGL + s];
                    unsigned long long xb = pack2(xv, xv);
                    fma2(acc[q][0], xb, wv.x);
                    fma2(acc[q][1], xb, wv.y);
                }
            }
        }

        // sequential hyperbolic chain over the 5 slots of this pass
        for (int q = 0; q < 5; ++q) {
            F4 t;
            unpack2(acc[q][0], t.x, t.y);
            unpack2(acc[q][1], t.z, t.w);
            F4 z; float sqz;
            expmap0_f(t, z, sqz);
            if (slot > 0) {
                F4 vel = logmap_f(z_prev, sq_prev, z, sqz);
                float wj = s_w[slot - 1];
                avg.x += wj * vel.x; avg.y += wj * vel.y;
                avg.z += wj * vel.z; avg.w += wj * vel.w;
                if (slot == 1) vel0 = vel;
                else if (slot == 2) vel1 = vel;
                else if (slot == 3) vel2 = vel;
            }
            z_prev = z; sq_prev = sqz;
            ++slot;
        }
    }

    // prediction iterations
    const float alpha = __ldg(alpha_p);
    const float w0  = s_w[0];
    const float w13 = s_w[13];
    F4 zl = z_prev; float sql = sq_prev;
#pragma unroll
    for (int k = 0; k < NPREDK; ++k) {
        F4 v = { avg.x * alpha, avg.y * alpha, avg.z * alpha, avg.w * alpha };
        F4 zn; float sqn;
        expmap_f(zl, sql, v, zn, sqn);

        // t0 = logmap0(z_next), stored for the batched MLP
        float n  = sqrtf(fmaxf(sqn, EPS2));
        float sc = atanhf(fminf(n, CLIPC)) / n;
        float4 outv = make_float4(zn.x * sc, zn.y * sc, zn.z * sc, zn.w * sc);
        *reinterpret_cast<float4*>(&g_t0[((size_t)k * NROWS + row) * DDIM + lane * 4]) = outv;

        if (k < 3) {
            F4 vn = logmap_f(zl, sql, zn, sqn);
            F4 vk = (k == 0 ? vel0 : (k == 1 ? vel1 : vel2));
            avg.x = (avg.x - w0 * vk.x) * DECAYF + w13 * vn.x;
            avg.y = (avg.y - w0 * vk.y) * DECAYF + w13 * vn.y;
            avg.z = (avg.z - w0 * vk.z) * DECAYF + w13 * vn.z;
            avg.w = (avg.w - w0 * vk.w) * DECAYF + w13 * vn.w;
        }
        zl = zn; sql = sqn;
    }
}

// ============================================================================
// Kernel 2: batched MLP  out = relu(t0 @ W1 + b1) @ W2 + b2, written transposed.
// Block: 256 threads, 32 rows (m = k*16384 + bf). N chunked by 128.
// ============================================================================
__global__ void __launch_bounds__(256)
mlp_kernel(const float* __restrict__ W1, const float* __restrict__ b1,
           const float* __restrict__ W2, const float* __restrict__ b2,
           float* __restrict__ out)
{
    __shared__ float As[32 * 128];      // A tile [r][k]
    __shared__ float Hs[32 * 132];      // hidden chunk [r][c], pad 132 (conflict-free)
    __shared__ float W2s[24 * 128];     // W2 chunk transposed [j][c]

    const int tid = threadIdx.x;
    const int m0  = blockIdx.x * 32;

    // load A tile (coalesced float4)
    {
        const float4* gsrc = reinterpret_cast<const float4*>(&g_t0[(size_t)m0 * DDIM]);
        float4* dst = reinterpret_cast<float4*>(As);
#pragma unroll
        for (int i = 0; i < 4; ++i)
            dst[tid + 256 * i] = __ldg(gsrc + tid + 256 * i);
    }
    __syncthreads();

    const int rg = tid >> 5;     // warp id: row-group (first gemm) / j-group (second)
    const int cg = tid & 31;     // lane: col-group (first gemm) / out row (second)

    unsigned long long accp[3] = {0ull, 0ull, 0ull};

#pragma unroll
    for (int nc = 0; nc < 4; ++nc) {
        __syncthreads();   // protect Hs/W2s from previous chunk's readers

        // stage W2 chunk transposed: W2s[j][c] = W2[nc*128 + c][j]
        for (int idx = tid; idx < 24 * 128; idx += 256) {
            int j = idx >> 7, c = idx & 127;
            W2s[idx] = __ldg(&W2[(size_t)(nc * 128 + c) * 24 + j]);
        }

        // ---- first GEMM: H[r][c] = relu(sum_k A[r][k] * W1[k][nc*128+c] + b1) ----
        unsigned long long hacc[4][2];
        {
            float4 b14 = __ldg(reinterpret_cast<const float4*>(b1 + nc * 128) + cg);
            unsigned long long h0 = pack2(b14.x, b14.y);
            unsigned long long h1 = pack2(b14.z, b14.w);
#pragma unroll
            for (int i = 0; i < 4; ++i) { hacc[i][0] = h0; hacc[i][1] = h1; }
        }
        const float* w1p = W1 + nc * 128;
#pragma unroll 2
        for (int k4 = 0; k4 < 32; ++k4) {
            const int k = k4 * 4;
            float4 a4[4];
#pragma unroll
            for (int i = 0; i < 4; ++i)
                a4[i] = *reinterpret_cast<const float4*>(&As[(rg * 4 + i) * 128 + k]);
#pragma unroll
            for (int kk = 0; kk < 4; ++kk) {
                ulonglong2 wv = __ldg(
                    reinterpret_cast<const ulonglong2*>(w1p + (size_t)(k + kk) * HDIM) + cg);
#pragma unroll
                for (int i = 0; i < 4; ++i) {
                    float a = (kk == 0 ? a4[i].x : kk == 1 ? a4[i].y :
                               kk == 2 ? a4[i].z : a4[i].w);
                    unsigned long long ab = pack2(a, a);
                    fma2(hacc[i][0], ab, wv.x);
                    fma2(hacc[i][1], ab, wv.y);
                }
            }
        }
        // relu + store hidden chunk
#pragma unroll
        for (int i = 0; i < 4; ++i) {
            float h0, h1, h2, h3;
            unpack2(hacc[i][0], h0, h1);
            unpack2(hacc[i][1], h2, h3);
            float4 hv = make_float4(fmaxf(h0, 0.f), fmaxf(h1, 0.f),
                                    fmaxf(h2, 0.f), fmaxf(h3, 0.f));
            *reinterpret_cast<float4*>(&Hs[(rg * 4 + i) * 132 + cg * 4]) = hv;
        }
        __syncthreads();

        // ---- second GEMM: out[r][j] += sum_c H[r][c] * W2[c][j] ----
#pragma unroll 4
        for (int c4 = 0; c4 < 32; ++c4) {
            const int c = c4 * 4;
            float4 h4 = *reinterpret_cast<const float4*>(&Hs[cg * 132 + c]);
            unsigned long long hA = pack2(h4.x, h4.y);
            unsigned long long hB = pack2(h4.z, h4.w);
#pragma unroll
            for (int jj = 0; jj < 3; ++jj) {
                ulonglong2 wv = *reinterpret_cast<const ulonglong2*>(
                    &W2s[(rg * 3 + jj) * 128 + c]);
                fma2(accp[jj], hA, wv.x);
                fma2(accp[jj], hB, wv.y);
            }
        }
    }

    // write transposed output: out[b, k*24 + j, f]
    const int kidx = m0 >> 14;          // which prediction step
    const int bf0  = m0 & 16383;
    const int bb   = bf0 >> 7;
    const int f    = (bf0 & 127) + cg;  // 32-row tiles never cross a b boundary
#pragma unroll
    for (int jj = 0; jj < 3; ++jj) {
        int j = rg * 3 + jj;
        float s0, s1;
        unpack2(accp[jj], s0, s1);
        float val = __ldg(&b2[j]) + s0 + s1;
        out[((size_t)bb * 96 + kidx * 24 + j) * 128 + f] = val;
    }
}

// ============================================================================
extern "C" void kernel_launch(void* const* d_in, const int* in_sizes, int n_in,
                              void* d_out, int out_size) {
    const float* trend   = (const float*)d_in[0];
    const float* scoarse = (const float*)d_in[1];
    const float* sfine   = (const float*)d_in[2];
    const float* resid   = (const float*)d_in[3];
    const float* W_t = (const float*)d_in[4];
    const float* b_t = (const float*)d_in[5];
    const float* W_c = (const float*)d_in[6];
    const float* b_c = (const float*)d_in[7];
    const float* W_f = (const float*)d_in[8];
    const float* b_f = (const float*)d_in[9];
    const float* W_r = (const float*)d_in[10];
    const float* b_r = (const float*)d_in[11];
    const float* alpha = (const float*)d_in[12];
    const float* W1 = (const float*)d_in[13];
    const float* b1 = (const float*)d_in[14];
    const float* W2 = (const float*)d_in[15];
    const float* b2 = (const float*)d_in[16];

    latent_kernel<<<NROWS / 8, 256>>>(trend, scoarse, sfine, resid,
                                      W_t, b_t, W_c, b_c, W_f, b_f, W_r, b_r,
                                      alpha);
    mlp_kernel<<<(NPREDK * NROWS) / 32, 256>>>(W1, b1, W2, b2, (float*)d_out);
}

// round 2
// speedup vs baseline: 1.5260x; 1.5260x over previous
#include <cuda_runtime.h>

// ---------------- problem constants ----------------
#define BATCH   128
#define LTOT    720
#define FEAT    128
#define SEGL    24
#define WINN    15
#define NPREDK  4
#define DDIM    128
#define HDIM    512
#define NROWS   (BATCH*FEAT)          // 16384
#define EPSC    1e-6f
#define EPS2    1e-12f
#define MAXNC   0.99999f              // 1 - 1e-5
#define CLIPC   0.99999988f           // float32(1 - 1e-7)
#define DECAYF  0.9f

// t0 latents buffer: [k][bf][d]  (33.5 MB, device global scratch -- no allocs)
__device__ float g_t0[(size_t)NPREDK * NROWS * DDIM];

// ---------------- f32x2 packed-FMA helpers ----------------
static __device__ __forceinline__ unsigned long long pack2(float x, float y) {
    unsigned long long r;
    asm("mov.b64 %0, {%1,%2};" : "=l"(r) : "f"(x), "f"(y));
    return r;
}
static __device__ __forceinline__ void unpack2(unsigned long long a, float &x, float &y) {
    asm("mov.b64 {%0,%1}, %2;" : "=f"(x), "=f"(y) : "l"(a));
}
static __device__ __forceinline__ void fma2(unsigned long long &a,
                                            unsigned long long b,
                                            unsigned long long c) {
    asm("fma.rn.f32x2 %0, %1, %2, %0;" : "+l"(a) : "l"(b), "l"(c));
}

// ---------------- warp math helpers ----------------
static __device__ __forceinline__ float wred(float v) {
#pragma unroll
    for (int o = 16; o > 0; o >>= 1) v += __shfl_xor_sync(0xffffffffu, v, o);
    return v;
}

struct F4 { float x, y, z, w; };

static __device__ __forceinline__ float dotred(const F4 &a, const F4 &b) {
    return wred(a.x*b.x + a.y*b.y + a.z*b.z + a.w*b.w);
}

// logmap(x, y) on the Poincare ball (C=1)
static __device__ __forceinline__ F4 logmap_f(const F4 &x, float sqx,
                                              const F4 &y, float sqy) {
    float xy  = dotred(x, y);
    float txy = -2.0f * xy;
    float cx  = 1.0f + txy + sqy;
    float cy  = 1.0f - sqx;
    float den = fmaxf(1.0f + txy + sqx*sqy, EPSC);
    float inv = 1.0f / den;
    F4 d;
    d.x = (cy*y.x - cx*x.x) * inv;
    d.y = (cy*y.y - cx*x.y) * inv;
    d.z = (cy*y.z - cx*x.z) * inv;
    d.w = (cy*y.w - cx*x.w) * inv;
    float sqd = dotred(d, d);
    float nd  = sqrtf(fmaxf(sqd, EPS2));
    float s   = fmaxf(cy, EPSC) * atanhf(fminf(nd, CLIPC)) / nd;
    F4 r = { d.x*s, d.y*s, d.z*s, d.w*s };
    return r;
}

// expmap0(v) followed by _project; returns z and ||z||^2
static __device__ __forceinline__ void expmap0_f(const F4 &t, F4 &z, float &sqz) {
    float sq = dotred(t, t);
    float n  = sqrtf(fmaxf(sq, EPS2));
    float sc = tanhf(n) / n;
    F4 r = { t.x*sc, t.y*sc, t.z*sc, t.w*sc };
    float sqr = dotred(r, r);
    float nr  = sqrtf(fmaxf(sqr, EPS2));
    if (nr > MAXNC) {
        float s = MAXNC / nr;
        r.x *= s; r.y *= s; r.z *= s; r.w *= s;
        sqr *= s * s;
    }
    z = r; sqz = sqr;
}

// expmap(x, v) followed by _project; returns z and ||z||^2
static __device__ __forceinline__ void expmap_f(const F4 &x, float sqx, const F4 &v,
                                                F4 &zout, float &sqout) {
    float m   = fmaxf(1.0f - sqx, EPSC);
    float sqv = dotred(v, v);
    float nv  = sqrtf(fmaxf(sqv, EPS2));
    float th  = tanhf(nv / m);
    float sc  = th / nv;
    F4 sec = { v.x*sc, v.y*sc, v.z*sc, v.w*sc };
    float xy = dotred(x, sec);
    float y2 = dotred(sec, sec);
    float ca  = 1.0f + 2.0f*xy + y2;
    float cb  = 1.0f - sqx;
    float den = fmaxf(1.0f + 2.0f*xy + sqx*y2, EPSC);
    float inv = 1.0f / den;
    F4 r = { (ca*x.x + cb*sec.x)*inv, (ca*x.y + cb*sec.y)*inv,
             (ca*x.z + cb*sec.z)*inv, (ca*x.w + cb*sec.w)*inv };
    float sqr = dotred(r, r);
    float nr  = sqrtf(fmaxf(sqr, EPS2));
    if (nr > MAXNC) {
        float s = MAXNC / nr;
        r.x *= s; r.y *= s; r.z *= s; r.w *= s;
        sqr *= s * s;
    }
    zout = r; sqout = sqr;
}

// ============================================================================
// Kernel 1: fused tan-GEMV + expmap0 + hyperbolic velocity recurrence.
// One warp per row (bf). The 8 warps of a block share the same b and own 8
// CONSECUTIVE f, so input loads are block-cooperative and coalesced
// (ff = idx&7 fastest -> 4 fully-used 32B sectors per warp-instruction,
// instead of a stride-512B gather touching 32 lines).
// ============================================================================
#define SXP 484   // tile row pitch: 484 mod 32 = 4 -> 8 ff-rows hit distinct banks

__global__ void __launch_bounds__(256)
latent_kernel(const float* __restrict__ trend,  const float* __restrict__ scoarse,
              const float* __restrict__ sfine,  const float* __restrict__ resid,
              const float* __restrict__ W_t, const float* __restrict__ b_t,
              const float* __restrict__ W_c, const float* __restrict__ b_c,
              const float* __restrict__ W_f, const float* __restrict__ b_f,
              const float* __restrict__ W_r, const float* __restrict__ b_r,
              const float* __restrict__ alpha_p)
{
    __shared__ float sX[8][SXP];   // per-warp-row: 4 streams x 120 timesteps
    __shared__ float s_w[16];

    const int tid  = threadIdx.x;
    const int wid  = tid >> 5;
    const int lane = tid & 31;

    if (tid == 0) {
        float ws[14]; float wv = 1.0f;
        for (int j = 13; j >= 0; --j) { ws[j] = wv; wv *= DECAYF; }
        float s = 0.0f;
        for (int j = 0; j < 14; ++j) s += ws[j];
        for (int j = 0; j < 14; ++j) s_w[j] = ws[j] / s;
    }

    const int row  = blockIdx.x * 8 + wid;
    const int b    = row >> 7;
    const int f0   = (blockIdx.x * 8) & 127;   // first f of this block's octet
    const size_t base_b = (size_t)b * LTOT * FEAT + f0;

    // combined bias (b_t + b_c + b_f + b_r), 4 comps per thread
    F4 bias;
    {
        float4 t1 = __ldg(reinterpret_cast<const float4*>(b_t) + lane);
        float4 t2 = __ldg(reinterpret_cast<const float4*>(b_c) + lane);
        float4 t3 = __ldg(reinterpret_cast<const float4*>(b_f) + lane);
        float4 t4 = __ldg(reinterpret_cast<const float4*>(b_r) + lane);
        bias.x = t1.x + t2.x + t3.x + t4.x;
        bias.y = t1.y + t2.y + t3.y + t4.y;
        bias.z = t1.z + t2.z + t3.z + t4.z;
        bias.w = t1.w + t2.w + t3.w + t4.w;
    }
    const unsigned long long bias01 = pack2(bias.x, bias.y);
    const unsigned long long bias23 = pack2(bias.z, bias.w);

    F4 z_prev = {0,0,0,0}; float sq_prev = 0.0f;
    F4 avg = {0,0,0,0};
    F4 vel0 = {0,0,0,0}, vel1 = {0,0,0,0}, vel2 = {0,0,0,0};
    int slot = 0;

    for (int p = 0; p < 3; ++p) {
        __syncthreads();
        const int l0 = 360 + p * 120;   // 5 contiguous segments per pass

        // block-cooperative coalesced load: element (i, ff) of each stream
#pragma unroll
        for (int st = 0; st < 4; ++st) {
            const float* src = (st == 0 ? trend : st == 1 ? scoarse :
                                st == 2 ? sfine : resid);
#pragma unroll
            for (int it = 0; it < 4; ++it) {
                int idx = tid + it * 256;
                if (idx < 960) {
                    int ff = idx & 7;
                    int i  = idx >> 3;
                    sX[ff][st * 120 + i] =
                        __ldg(&src[base_b + (size_t)(l0 + i) * FEAT + ff]);
                }
            }
        }
        __syncthreads();

        unsigned long long acc[5][2];
#pragma unroll
        for (int q = 0; q < 5; ++q) { acc[q][0] = bias01; acc[q][1] = bias23; }

#pragma unroll
        for (int st = 0; st < 4; ++st) {
            const float* W = (st == 0 ? W_t : st == 1 ? W_c : st == 2 ? W_f : W_r);
#pragma unroll 4
            for (int s = 0; s < SEGL; ++s) {
                ulonglong2 wv = __ldg(reinterpret_cast<const ulonglong2*>(W + s * DDIM) + lane);
#pragma unroll
                for (int q = 0; q < 5; ++q) {
                    float xv = sX[wid][st * 120 + q * SEGL + s];
                    unsigned long long xb = pack2(xv, xv);
                    fma2(acc[q][0], xb, wv.x);
                    fma2(acc[q][1], xb, wv.y);
                }
            }
        }

        // sequential hyperbolic chain over the 5 slots of this pass
        for (int q = 0; q < 5; ++q) {
            F4 t;
            unpack2(acc[q][0], t.x, t.y);
            unpack2(acc[q][1], t.z, t.w);
            F4 z; float sqz;
            expmap0_f(t, z, sqz);
            if (slot > 0) {
                F4 vel = logmap_f(z_prev, sq_prev, z, sqz);
                float wj = s_w[slot - 1];
                avg.x += wj * vel.x; avg.y += wj * vel.y;
                avg.z += wj * vel.z; avg.w += wj * vel.w;
                if (slot == 1) vel0 = vel;
                else if (slot == 2) vel1 = vel;
                else if (slot == 3) vel2 = vel;
            }
            z_prev = z; sq_prev = sqz;
            ++slot;
        }
    }

    // prediction iterations
    const float alpha = __ldg(alpha_p);
    const float w0  = s_w[0];
    const float w13 = s_w[13];
    F4 zl = z_prev; float sql = sq_prev;
#pragma unroll
    for (int k = 0; k < NPREDK; ++k) {
        F4 v = { avg.x * alpha, avg.y * alpha, avg.z * alpha, avg.w * alpha };
        F4 zn; float sqn;
        expmap_f(zl, sql, v, zn, sqn);

        // t0 = logmap0(z_next), stored for the batched MLP
        float n  = sqrtf(fmaxf(sqn, EPS2));
        float sc = atanhf(fminf(n, CLIPC)) / n;
        float4 outv = make_float4(zn.x * sc, zn.y * sc, zn.z * sc, zn.w * sc);
        *reinterpret_cast<float4*>(&g_t0[((size_t)k * NROWS + row) * DDIM + lane * 4]) = outv;

        if (k < 3) {
            F4 vn = logmap_f(zl, sql, zn, sqn);
            F4 vk = (k == 0 ? vel0 : (k == 1 ? vel1 : vel2));
            avg.x = (avg.x - w0 * vk.x) * DECAYF + w13 * vn.x;
            avg.y = (avg.y - w0 * vk.y) * DECAYF + w13 * vn.y;
            avg.z = (avg.z - w0 * vk.z) * DECAYF + w13 * vn.z;
            avg.w = (avg.w - w0 * vk.w) * DECAYF + w13 * vn.w;
        }
        zl = zn; sql = sqn;
    }
}

// ============================================================================
// Kernel 2: batched MLP  out = relu(t0 @ W1 + b1) @ W2 + b2, written transposed.
// 256 threads, 64-row M-tile (8 rows/thread), N chunked by 128.
// ============================================================================
__global__ void __launch_bounds__(256, 2)
mlp_kernel(const float* __restrict__ W1, const float* __restrict__ b1,
           const float* __restrict__ W2, const float* __restrict__ b2,
           float* __restrict__ out)
{
    __shared__ float As[64 * 128];      // A tile [r][k]          (32 KB)
    __shared__ float Hs[64 * 132];      // hidden chunk [r][c]    (33.8 KB, pad 132)
    __shared__ float W2s[24 * 128];     // W2 chunk transposed [j][c] (12 KB)

    const int tid = threadIdx.x;
    const int m0  = blockIdx.x * 64;

    // load A tile (coalesced float4): 2048 float4 / 256 threads = 8 each
    {
        const float4* gsrc = reinterpret_cast<const float4*>(&g_t0[(size_t)m0 * DDIM]);
        float4* dst = reinterpret_cast<float4*>(As);
#pragma unroll
        for (int i = 0; i < 8; ++i)
            dst[tid + 256 * i] = __ldg(gsrc + tid + 256 * i);
    }

    const int rg = tid >> 5;     // warp id: row-group (gemm1) / j-group (gemm2)
    const int cg = tid & 31;     // lane: col-group (gemm1) / out row (gemm2)

    unsigned long long accp[2][3] = {{0ull,0ull,0ull},{0ull,0ull,0ull}};

#pragma unroll
    for (int nc = 0; nc < 4; ++nc) {
        __syncthreads();   // A ready (nc=0) / Hs+W2s readers done (nc>0)

        // stage W2 chunk transposed: W2s[j][c] = W2[nc*128 + c][j]
        for (int idx = tid; idx < 24 * 128; idx += 256) {
            int j = idx >> 7, c = idx & 127;
            W2s[idx] = __ldg(&W2[(size_t)(nc * 128 + c) * 24 + j]);
        }

        // ---- GEMM1: H[r][c] = relu(sum_k A[r][k] * W1[k][nc*128+c] + b1) ----
        unsigned long long hacc[8][2];
        {
            float4 b14 = __ldg(reinterpret_cast<const float4*>(b1 + nc * 128) + cg);
            unsigned long long h0 = pack2(b14.x, b14.y);
            unsigned long long h1 = pack2(b14.z, b14.w);
#pragma unroll
            for (int i = 0; i < 8; ++i) { hacc[i][0] = h0; hacc[i][1] = h1; }
        }
        const float* w1p = W1 + nc * 128;
#pragma unroll 2
        for (int k4 = 0; k4 < 32; ++k4) {
            const int k = k4 * 4;
            float4 a4[8];
#pragma unroll
            for (int i = 0; i < 8; ++i)
                a4[i] = *reinterpret_cast<const float4*>(&As[(rg * 8 + i) * 128 + k]);
#pragma unroll
            for (int kk = 0; kk < 4; ++kk) {
                ulonglong2 wv = __ldg(
                    reinterpret_cast<const ulonglong2*>(w1p + (size_t)(k + kk) * HDIM) + cg);
#pragma unroll
                for (int i = 0; i < 8; ++i) {
                    float a = (kk == 0 ? a4[i].x : kk == 1 ? a4[i].y :
                               kk == 2 ? a4[i].z : a4[i].w);
                    unsigned long long ab = pack2(a, a);
                    fma2(hacc[i][0], ab, wv.x);
                    fma2(hacc[i][1], ab, wv.y);
                }
            }
        }
        // relu + store hidden chunk
#pragma unroll
        for (int i = 0; i < 8; ++i) {
            float h0, h1, h2, h3;
            unpack2(hacc[i][0], h0, h1);
            unpack2(hacc[i][1], h2, h3);
            float4 hv = make_float4(fmaxf(h0, 0.f), fmaxf(h1, 0.f),
                                    fmaxf(h2, 0.f), fmaxf(h3, 0.f));
            *reinterpret_cast<float4*>(&Hs[(rg * 8 + i) * 132 + cg * 4]) = hv;
        }
        __syncthreads();

        // ---- GEMM2: out[r][j] += sum_c H[r][c] * W2[c][j] ----
#pragma unroll 4
        for (int c4 = 0; c4 < 32; ++c4) {
            const int c = c4 * 4;
            ulonglong2 wv0 = *reinterpret_cast<const ulonglong2*>(&W2s[(rg * 3 + 0) * 128 + c]);
            ulonglong2 wv1 = *reinterpret_cast<const ulonglong2*>(&W2s[(rg * 3 + 1) * 128 + c]);
            ulonglong2 wv2 = *reinterpret_cast<const ulonglong2*>(&W2s[(rg * 3 + 2) * 128 + c]);
#pragma unroll
            for (int rh = 0; rh < 2; ++rh) {
                float4 h4 = *reinterpret_cast<const float4*>(&Hs[(rh * 32 + cg) * 132 + c]);
                unsigned long long hA = pack2(h4.x, h4.y);
                unsigned long long hB = pack2(h4.z, h4.w);
                fma2(accp[rh][0], hA, wv0.x); fma2(accp[rh][0], hB, wv0.y);
                fma2(accp[rh][1], hA, wv1.x); fma2(accp[rh][1], hB, wv1.y);
                fma2(accp[rh][2], hA, wv2.x); fma2(accp[rh][2], hB, wv2.y);
            }
        }
    }

    // write transposed output: out[b, kidx*24 + j, f]
    const int kidx = m0 >> 14;          // prediction step (64 | 16384, no straddle)
    const int bf0  = m0 & 16383;
    const int bb   = bf0 >> 7;
    const int f0   = bf0 & 127;         // 64-row tiles never cross a b boundary
#pragma unroll
    for (int rh = 0; rh < 2; ++rh) {
#pragma unroll
        for (int jj = 0; jj < 3; ++jj) {
            int j = rg * 3 + jj;
            float s0, s1;
            unpack2(accp[rh][jj], s0, s1);
            float val = __ldg(&b2[j]) + s0 + s1;
            out[((size_t)bb * 96 + kidx * 24 + j) * 128 + f0 + rh * 32 + cg] = val;
        }
    }
}

// ============================================================================
extern "C" void kernel_launch(void* const* d_in, const int* in_sizes, int n_in,
                              void* d_out, int out_size) {
    const float* trend   = (const float*)d_in[0];
    const float* scoarse = (const float*)d_in[1];
    const float* sfine   = (const float*)d_in[2];
    const float* resid   = (const float*)d_in[3];
    const float* W_t = (const float*)d_in[4];
    const float* b_t = (const float*)d_in[5];
    const float* W_c = (const float*)d_in[6];
    const float* b_c = (const float*)d_in[7];
    const float* W_f = (const float*)d_in[8];
    const float* b_f = (const float*)d_in[9];
    const float* W_r = (const float*)d_in[10];
    const float* b_r = (const float*)d_in[11];
    const float* alpha = (const float*)d_in[12];
    const float* W1 = (const float*)d_in[13];
    const float* b1 = (const float*)d_in[14];
    const float* W2 = (const float*)d_in[15];
    const float* b2 = (const float*)d_in[16];

    latent_kernel<<<NROWS / 8, 256>>>(trend, scoarse, sfine, resid,
                                      W_t, b_t, W_c, b_c, W_f, b_f, W_r, b_r,
                                      alpha);
    mlp_kernel<<<(NPREDK * NROWS) / 64, 256>>>(W1, b1, W2, b2, (float*)d_out);
}